// round 11
// baseline (speedup 1.0000x reference)
#include <cuda_runtime.h>
#include <cuda_fp16.h>
#include <math.h>

#define IMW 1024
#define IMH 1024
#define NB  8
#define OW  128
#define OH  32
#define LW  160          // luma tile cols: global x in [x0-16, x0+144)
#define LH  62           // luma tile rows: global y in [y0-15, y0+47)
#define SWH 160          // row stride: halves (sLuma) / half2 (pair planes)
#define PROWS (OH/2)     // 16 pair-rows
// smem: sLuma 62*160*2 + 2 pair planes 16*160*4 = 19840 + 20480 = 40320 B
#define SMEM_BYTES (LH*SWH*2 + 2*PROWS*SWH*4)

// fp16x2 immediates (same weight both lanes).
// 31-tap gaussian (sigma=8), normalized, k=0..30 (center 15)
__device__ constexpr unsigned G31X2[31] = {
    0x20A520A5u, 0x21D421D4u, 0x23322332u, 0x24602460u, 0x253C253Cu, 0x262B262Bu,
    0x27282728u, 0x28162816u, 0x28982898u, 0x29162916u, 0x298B298Bu, 0x29F229F2u,
    0x2A482A48u, 0x2A882A88u, 0x2AAF2AAFu, 0x2ABD2ABDu, 0x2AAF2AAFu, 0x2A882A88u,
    0x2A482A48u, 0x29F229F2u, 0x298B298Bu, 0x29162916u, 0x28982898u, 0x28162816u,
    0x27282728u, 0x262B262Bu, 0x253C253Cu, 0x24602460u, 0x23322332u, 0x21D421D4u,
    0x20A520A5u
};
// 7-tap gaussian (sigma=1.5), normalized
__device__ constexpr unsigned G7X2[7] = {
    0x28B028B0u, 0x2F1F2F1Fu, 0x32F032F0u, 0x34553455u,
    0x32F032F0u, 0x2F1F2F1Fu, 0x28B028B0u
};

__device__ __forceinline__ __half2 hc(unsigned b) {
    __half2_raw r;
    r.x = (unsigned short)(b & 0xFFFFu);
    r.y = (unsigned short)(b >> 16);
    return __half2(r);
}

__global__ __launch_bounds__(256, 4)
void clarity_texture_kernel(const float* __restrict__ x,
                            const float* __restrict__ clar,
                            const float* __restrict__ tex,
                            float* __restrict__ out) {
    extern __shared__ __half smem[];
    __half*  sLuma = smem;                              // LH x SWH halves
    __half2* sPV31 = (__half2*)(smem + LH * SWH);       // PROWS x SWH half2 (rows 2i,2i+1)
    __half2* sPV7  = sPV31 + PROWS * SWH;               // PROWS x SWH half2

    const int tid = threadIdx.x;
    const int x0  = blockIdx.x * OW;
    const int y0  = blockIdx.y * OH;
    const int b   = blockIdx.z;

    const float ca = tanhf(*clar) * 0.5f;
    const float ta = tanhf(*tex) * 0.3f;

    const size_t plane = (size_t)IMH * IMW;
    const float* xb = x + (size_t)b * 3 * plane;
    float* ob = out + (size_t)b * 3 * plane;

    // ---- Phase 1: luma tile with halo (fp16 store), float4 global loads ----
    for (int i = tid; i < LH * (LW / 4); i += 256) {
        int row = i / (LW / 4);
        int cc  = i % (LW / 4);
        int gy  = y0 - 15 + row;
        int gx  = x0 - 16 + cc * 4;
        float4 l4 = make_float4(0.f, 0.f, 0.f, 0.f);
        if ((unsigned)gy < IMH && (unsigned)gx < IMW) {
            size_t idx = (size_t)gy * IMW + gx;
            float4 r4 = *(const float4*)&xb[idx];
            float4 g4 = *(const float4*)&xb[idx + plane];
            float4 b4 = *(const float4*)&xb[idx + 2 * plane];
            l4.x = 0.2126f * r4.x + 0.7152f * g4.x + 0.0722f * b4.x;
            l4.y = 0.2126f * r4.y + 0.7152f * g4.y + 0.0722f * b4.y;
            l4.z = 0.2126f * r4.z + 0.7152f * g4.z + 0.0722f * b4.z;
            l4.w = 0.2126f * r4.w + 0.7152f * g4.w + 0.0722f * b4.w;
        }
        __half* dst = &sLuma[row * SWH + cc * 4];
        *(__half2*)(dst)     = __floats2half2_rn(l4.x, l4.y);
        *(__half2*)(dst + 2) = __floats2half2_rn(l4.z, l4.w);
    }
    __syncthreads();

    // ---- Phase 2: vertical 31-tap + 7-tap blurs, HFMA2 over 2 cols x 4 rows.
    // Store transposed into row-pair planes.
    for (int s = tid; s < (SWH / 2) * (OH / 4); s += 256) {   // 80*8 = 640
        int c  = s % (SWH / 2);          // column pair (cols 2c, 2c+1)
        int r0 = (s / (SWH / 2)) * 4;    // output rows r0..r0+3
        __half2 a[4], w[4];
        #pragma unroll
        for (int o = 0; o < 4; o++) { a[o] = hc(0u); w[o] = hc(0u); }
        #pragma unroll
        for (int k = 0; k < 34; k++) {
            __half2 v = *(const __half2*)&sLuma[(r0 + k) * SWH + 2 * c];
            #pragma unroll
            for (int o = 0; o < 4; o++) {
                int i31 = k - o;
                if (i31 >= 0 && i31 < 31) a[o] = __hfma2(v, hc(G31X2[i31]), a[o]);
                int j7 = k - 12 - o;
                if (j7 >= 0 && j7 < 7)    w[o] = __hfma2(v, hc(G7X2[j7]), w[o]);
            }
        }
        // transpose: per column, pack (row r0,r0+1) and (r0+2,r0+3)
        int p0 = r0 >> 1;   // even pair-row index
        __half2* d31 = &sPV31[p0 * SWH + 2 * c];
        __half2* d7  = &sPV7 [p0 * SWH + 2 * c];
        d31[0]   = __lows2half2 (a[0], a[1]);
        d31[1]   = __highs2half2(a[0], a[1]);
        d31[SWH]     = __lows2half2 (a[2], a[3]);
        d31[SWH + 1] = __highs2half2(a[2], a[3]);
        d7[0]    = __lows2half2 (w[0], w[1]);
        d7[1]    = __highs2half2(w[0], w[1]);
        d7[SWH]      = __lows2half2 (w[2], w[3]);
        d7[SWH + 1]  = __highs2half2(w[2], w[3]);
    }
    __syncthreads();

    // ---- Phase 3: horizontal blurs (HFMA2, 2 rows x 8 cols per thread) ----
    {
        const int i  = tid >> 4;          // pair-row 0..15 (output rows 2i, 2i+1)
        const int c0 = (tid & 15) * 8;    // output col strip

        // 31-tap: out col c0+o taps cols c0+1+o+k (k=0..30); window c0..c0+39
        __half2 acc31[8], acc7[8];
        #pragma unroll
        for (int o = 0; o < 8; o++) { acc31[o] = hc(0u); acc7[o] = hc(0u); }

        const uint4* p31 = (const uint4*)&sPV31[i * SWH + c0];
        #pragma unroll
        for (int chk = 0; chk < 10; chk++) {
            uint4 u = p31[chk];
            unsigned uu[4] = {u.x, u.y, u.z, u.w};
            #pragma unroll
            for (int q = 0; q < 4; q++) {
                __half2 t = hc(uu[q]);
                int m = chk * 4 + q;
                #pragma unroll
                for (int o = 0; o < 8; o++) {
                    int k = m - 1 - o;
                    if (k >= 0 && k < 31) acc31[o] = __hfma2(t, hc(G31X2[k]), acc31[o]);
                }
            }
        }

        // 7-tap: out col c0+o taps cols c0+13+o+j (j=0..6); aligned from c0+12
        const uint4* p7 = (const uint4*)&sPV7[i * SWH + c0 + 12];
        #pragma unroll
        for (int chk = 0; chk < 4; chk++) {
            uint4 u = p7[chk];
            unsigned uu[4] = {u.x, u.y, u.z, u.w};
            #pragma unroll
            for (int q = 0; q < 4; q++) {
                __half2 t = hc(uu[q]);
                int l = chk * 4 + q;         // tap col = c0 + 12 + l
                #pragma unroll
                for (int o = 0; o < 8; o++) {
                    int j = l - 1 - o;
                    if (j >= 0 && j < 7) acc7[o] = __hfma2(t, hc(G7X2[j]), acc7[o]);
                }
            }
        }

        // center luma for both rows (tile col = out col + 16)
        __half l0h[8], l1h[8];
        *(uint4*)l0h = *(const uint4*)&sLuma[(2 * i + 15) * SWH + c0 + 16];
        *(uint4*)l1h = *(const uint4*)&sLuma[(2 * i + 16) * SWH + c0 + 16];

        float r0v[8], r1v[8];
        #pragma unroll
        for (int o = 0; o < 8; o++) {
            float2 m31 = __half22float2(acc31[o]);   // .x row 2i, .y row 2i+1
            float2 m7  = __half22float2(acc7[o]);
            float l0 = __half2float(l0h[o]);
            float l1 = __half2float(l1h[o]);
            float le0 = l0 + ca * (l0 - m31.x) + ta * (l0 - m7.x);
            float le1 = l1 + ca * (l1 - m31.y) + ta * (l1 - m7.y);
            r0v[o] = __fdividef(le0 + 1e-6f, l0 + 1e-6f);
            r1v[o] = __fdividef(le1 + 1e-6f, l1 + 1e-6f);
        }

        const int gy = y0 + 2 * i;
        const int gx = x0 + c0;
        size_t idx0 = (size_t)gy * IMW + gx;
        size_t idx1 = idx0 + IMW;
        #pragma unroll
        for (int ch = 0; ch < 3; ch++) {
            size_t o0 = idx0 + (size_t)ch * plane;
            size_t o1 = idx1 + (size_t)ch * plane;
            float4 xa = *(const float4*)&xb[o0];
            float4 xc = *(const float4*)&xb[o0 + 4];
            float4 ya = *(const float4*)&xb[o1];
            float4 yc = *(const float4*)&xb[o1 + 4];
            float4 ra, rc, sa, sc;
            ra.x = __saturatef(xa.x * r0v[0]); ra.y = __saturatef(xa.y * r0v[1]);
            ra.z = __saturatef(xa.z * r0v[2]); ra.w = __saturatef(xa.w * r0v[3]);
            rc.x = __saturatef(xc.x * r0v[4]); rc.y = __saturatef(xc.y * r0v[5]);
            rc.z = __saturatef(xc.z * r0v[6]); rc.w = __saturatef(xc.w * r0v[7]);
            sa.x = __saturatef(ya.x * r1v[0]); sa.y = __saturatef(ya.y * r1v[1]);
            sa.z = __saturatef(ya.z * r1v[2]); sa.w = __saturatef(ya.w * r1v[3]);
            sc.x = __saturatef(yc.x * r1v[4]); sc.y = __saturatef(yc.y * r1v[5]);
            sc.z = __saturatef(yc.z * r1v[6]); sc.w = __saturatef(yc.w * r1v[7]);
            *(float4*)&ob[o0]     = ra;
            *(float4*)&ob[o0 + 4] = rc;
            *(float4*)&ob[o1]     = sa;
            *(float4*)&ob[o1 + 4] = sc;
        }
    }
}

extern "C" void kernel_launch(void* const* d_in, const int* in_sizes, int n_in,
                              void* d_out, int out_size) {
    const float* x    = (const float*)d_in[0];
    const float* clar = (const float*)d_in[1];
    const float* tex  = (const float*)d_in[2];
    float* out = (float*)d_out;

    cudaFuncSetAttribute(clarity_texture_kernel,
                         cudaFuncAttributeMaxDynamicSharedMemorySize, SMEM_BYTES);

    dim3 grid(IMW / OW, IMH / OH, NB);
    clarity_texture_kernel<<<grid, 256, SMEM_BYTES>>>(x, clar, tex, out);
}